// round 1
// baseline (speedup 1.0000x reference)
#include <cuda_runtime.h>

// TemporalPSPGate: state_t = ALPHA*state_{t-1} + x_t ; out_t = x_t * sigmoid(state_t)
// Shapes: x [T=16, B=16, H=8, N=256, D=64] fp32. S = B*H*N*D = 2,097,152.
// Scan over T is sequential per spatial position; positions independent.
// Memory-bound: 256 MiB total traffic -> ~40 us at HBM ceiling.

#define TT 16
#define SPATIAL (16 * 8 * 256 * 64)      // 2,097,152
#define SPATIAL4 (SPATIAL / 4)           // 524,288 float4 lanes

__device__ __forceinline__ float fast_sigmoid(float s) {
    // 1 / (1 + exp(-s)) using MUFU EX2 path
    return 1.0f / (1.0f + __expf(-s));
}

__global__ __launch_bounds__(256) void psp_gate_kernel(
    const float4* __restrict__ x, float4* __restrict__ out)
{
    const int gid = blockIdx.x * blockDim.x + threadIdx.x;  // 0 .. SPATIAL4-1
    const float alpha = 0.60653065971263342360f;            // exp(-1/2)

    float4 st = make_float4(0.f, 0.f, 0.f, 0.f);

    #pragma unroll
    for (int t = 0; t < TT; t++) {
        const long long idx = (long long)t * SPATIAL4 + gid;
        float4 xv = x[idx];

        st.x = fmaf(alpha, st.x, xv.x);
        st.y = fmaf(alpha, st.y, xv.y);
        st.z = fmaf(alpha, st.z, xv.z);
        st.w = fmaf(alpha, st.w, xv.w);

        float4 ov;
        ov.x = xv.x * fast_sigmoid(st.x);
        ov.y = xv.y * fast_sigmoid(st.y);
        ov.z = xv.z * fast_sigmoid(st.z);
        ov.w = xv.w * fast_sigmoid(st.w);

        out[idx] = ov;
    }
}

extern "C" void kernel_launch(void* const* d_in, const int* in_sizes, int n_in,
                              void* d_out, int out_size) {
    const float4* x = (const float4*)d_in[0];
    float4* out = (float4*)d_out;
    const int threads = 256;
    const int blocks = SPATIAL4 / threads;   // 2048
    psp_gate_kernel<<<blocks, threads>>>(x, out);
}

// round 5
// speedup vs baseline: 1.0366x; 1.0366x over previous
#include <cuda_runtime.h>

// TemporalPSPGate: state_t = ALPHA*state_{t-1} + x_t ; out_t = x_t * sigmoid(state_t)
// x [T=16, B=16, H=8, N=256, D=64] fp32. Memory-bound: 256 MiB traffic.
// R1: depth-2 prefetch pipeline (raise per-warp MLP; ptxas kept MLP=1 at 32 regs),
//     streaming cache hints (.cs: no reuse of x or out), pointer-increment
//     addressing (t*8MiB strides don't fit LDG immediates -> was IMAD chains).

#define TT 16
#define SPATIAL4 ((16 * 8 * 256 * 64) / 4)   // 524,288 float4 lanes

__device__ __forceinline__ float fast_sigmoid(float s) {
    return 1.0f / (1.0f + __expf(-s));       // FMUL + MUFU.EX2 + FADD + MUFU.RCP
}

__global__ __launch_bounds__(256, 6) void psp_gate_kernel(
    const float4* __restrict__ x, float4* __restrict__ out)
{
    const int gid = blockIdx.x * blockDim.x + threadIdx.x;
    const float alpha = 0.60653065971263342360f;   // exp(-1/2)

    const float4* xp = x + gid;
    float4*       op = out + gid;

    float4 st = make_float4(0.f, 0.f, 0.f, 0.f);

    // Depth-2 rotating prefetch buffer: always 2 independent LDGs in flight.
    float4 buf0 = __ldcs(xp);
    float4 buf1 = __ldcs(xp + SPATIAL4);
    xp += 2 * (long long)SPATIAL4;

    #pragma unroll
    for (int t = 0; t < TT; t++) {
        float4 xv = (t & 1) ? buf1 : buf0;

        // Prefetch t+2 into the slot just consumed (issued before the
        // dependent compute chain so LDG sits high in the SASS).
        if (t + 2 < TT) {
            if (t & 1) buf1 = __ldcs(xp);
            else       buf0 = __ldcs(xp);
            xp += SPATIAL4;
        }

        st.x = fmaf(alpha, st.x, xv.x);
        st.y = fmaf(alpha, st.y, xv.y);
        st.z = fmaf(alpha, st.z, xv.z);
        st.w = fmaf(alpha, st.w, xv.w);

        float4 ov;
        ov.x = xv.x * fast_sigmoid(st.x);
        ov.y = xv.y * fast_sigmoid(st.y);
        ov.z = xv.z * fast_sigmoid(st.z);
        ov.w = xv.w * fast_sigmoid(st.w);

        __stcs(op, ov);
        op += SPATIAL4;
    }
}

extern "C" void kernel_launch(void* const* d_in, const int* in_sizes, int n_in,
                              void* d_out, int out_size) {
    const float4* x = (const float4*)d_in[0];
    float4* out = (float4*)d_out;
    const int threads = 256;
    const int blocks = SPATIAL4 / threads;   // 2048
    psp_gate_kernel<<<blocks, threads>>>(x, out);
}

// round 6
// speedup vs baseline: 1.0752x; 1.0372x over previous
#include <cuda_runtime.h>

// TemporalPSPGate: state_t = ALPHA*state_{t-1} + x_t ; out_t = x_t * sigmoid(state_t)
// x [T=16, B=16, H=8, N=256, D=64] fp32. Memory-bound: 256 MiB traffic.
// R1: depth-2 prefetch + .cs streaming hints + pointer-increment addressing.
// R5: sigmoid via single-MUFU tanh identity: sig(s) = 0.5*tanh(0.5s) + 0.5.
//     Halves MUFU pipe pressure (was 2 MUFU/elem = ~35% of runtime occupying
//     issue slots); warps park on memory sooner -> higher DRAM active%.
//     out = x*sig = fma(0.5x, tanh(0.5*st), 0.5x) -> FMUL,MUFU.TANH,FMUL,FFMA.

#define TT 16
#define SPATIAL4 ((16 * 8 * 256 * 64) / 4)   // 524,288 float4 lanes

__device__ __forceinline__ float tanh_approx(float s) {
    float r;
    asm("tanh.approx.f32 %0, %1;" : "=f"(r) : "f"(s));
    return r;
}

__global__ __launch_bounds__(256, 6) void psp_gate_kernel(
    const float4* __restrict__ x, float4* __restrict__ out)
{
    const int gid = blockIdx.x * blockDim.x + threadIdx.x;
    const float alpha = 0.60653065971263342360f;   // exp(-1/2)

    const float4* xp = x + gid;
    float4*       op = out + gid;

    float4 st = make_float4(0.f, 0.f, 0.f, 0.f);

    // Depth-2 rotating prefetch: always 2 independent LDG.128 in flight.
    float4 buf0 = __ldcs(xp);
    float4 buf1 = __ldcs(xp + SPATIAL4);
    xp += 2 * (long long)SPATIAL4;

    #pragma unroll
    for (int t = 0; t < TT; t++) {
        float4 xv = (t & 1) ? buf1 : buf0;

        if (t + 2 < TT) {
            if (t & 1) buf1 = __ldcs(xp);
            else       buf0 = __ldcs(xp);
            xp += SPATIAL4;
        }

        st.x = fmaf(alpha, st.x, xv.x);
        st.y = fmaf(alpha, st.y, xv.y);
        st.z = fmaf(alpha, st.z, xv.z);
        st.w = fmaf(alpha, st.w, xv.w);

        // sigmoid(s) = 0.5*tanh(0.5*s) + 0.5 ; out = x*sigmoid
        float hx_x = 0.5f * xv.x;
        float hx_y = 0.5f * xv.y;
        float hx_z = 0.5f * xv.z;
        float hx_w = 0.5f * xv.w;

        float4 ov;
        ov.x = fmaf(hx_x, tanh_approx(0.5f * st.x), hx_x);
        ov.y = fmaf(hx_y, tanh_approx(0.5f * st.y), hx_y);
        ov.z = fmaf(hx_z, tanh_approx(0.5f * st.z), hx_z);
        ov.w = fmaf(hx_w, tanh_approx(0.5f * st.w), hx_w);

        __stcs(op, ov);
        op += SPATIAL4;
    }
}

extern "C" void kernel_launch(void* const* d_in, const int* in_sizes, int n_in,
                              void* d_out, int out_size) {
    const float4* x = (const float4*)d_in[0];
    float4* out = (float4*)d_out;
    const int threads = 256;
    const int blocks = SPATIAL4 / threads;   // 2048
    psp_gate_kernel<<<blocks, threads>>>(x, out);
}